// round 4
// baseline (speedup 1.0000x reference)
#include <cuda_runtime.h>
#include <cuda_bf16.h>
#include <cstdint>

#define N1 262144
#define N2 65536
#define KNN 16
#define MPAIR (N2*KNN)
#define EPSV 1e-5f

// ---- static scratch (no runtime allocation allowed) ----
__device__ float g_upfeat[N2*64];   // relu(bn(x2@w2^T))
__device__ float g_pre[N2*64];      // x2-part of shrinker linear
__device__ float g_e[MPAIR];        // exp(logit)
__device__ float g_denom[N1];       // softmax denominator

__global__ void init_kernel() {
    int i = blockIdx.x * blockDim.x + threadIdx.x;
    if (i < N1) g_denom[i] = 0.0f;
}

// bf16 mma (baseline ISA, sm_80+; lowers to HMMA on sm_103 tensor pipe)
__device__ __forceinline__ void mma16816(float* d, const uint32_t* a, uint32_t b0, uint32_t b1) {
    asm volatile(
        "mma.sync.aligned.m16n8k16.row.col.f32.bf16.bf16.f32 "
        "{%0,%1,%2,%3}, {%4,%5,%6,%7}, {%8,%9}, {%0,%1,%2,%3};"
        : "+f"(d[0]), "+f"(d[1]), "+f"(d[2]), "+f"(d[3])
        : "r"(a[0]), "r"(a[1]), "r"(a[2]), "r"(a[3]), "r"(b0), "r"(b1));
}

// split (f0,f1) into packed bf16 hi-pair and lo-pair (residual)
__device__ __forceinline__ void split2(float f0, float f1, uint32_t& hi, uint32_t& lo) {
    __nv_bfloat16 h0 = __float2bfloat16_rn(f0);
    __nv_bfloat16 h1 = __float2bfloat16_rn(f1);
    __nv_bfloat162 hp; hp.x = h0; hp.y = h1;
    __nv_bfloat162 lp = __floats2bfloat162_rn(f0 - __bfloat162float(h0),
                                              f1 - __bfloat162float(h1));
    hi = *(uint32_t*)&hp;
    lo = *(uint32_t*)&lp;
}

// ===================== tensor-core fused Linear(64->64)+BN(+ReLU) =====================
// Block: 256 threads (8 warps), 128 points x 64 channels, K=64.
// Warp w: rows [m0, m0+16). Per-thread: 8 n-tiles x 4 f32 accumulators.
// A (x rows, bf16 hi/lo) in registers straight from global; B (BN-folded W,
// bf16 hi/lo pairs) in swizzled smem. 3 chains: Ah*Bh + Ah*Bl + Al*Bh.
// DST: 0 -> outp, 1 -> g_upfeat, 2 -> g_pre.
template<bool RELU, int DST>
__global__ void __launch_bounds__(256)
gemm_mma_kernel(const float* __restrict__ x,
                const float* __restrict__ w, int wstride, int wcol0,
                const float* __restrict__ bb,
                const float* __restrict__ gg,
                const float* __restrict__ be,
                const float* __restrict__ mm,
                const float* __restrict__ vv,
                float* __restrict__ outp)
{
    __shared__ uint32_t packB[64 * 64];   // rows 0-31: Bh kpairs, rows 32-63: Bl; 16 KB
    __shared__ float fb[64];

    const int tid  = threadIdx.x;
    const int wid  = tid >> 5;
    const int lane = tid & 31;
    const int gq   = lane >> 2;   // 0..7
    const int tq   = lane & 3;    // 0..3

    if (tid < 64) {
        float s = gg[tid] * rsqrtf(vv[tid] + EPSV);
        fb[tid] = (bb[tid] - mm[tid]) * s + be[tid];
    }

    // ---- fill B: pack(Wf[n][2kp], Wf[n][2kp+1]), hi rows 0-31, lo rows 32-63 ----
    #pragma unroll
    for (int it = 0; it < 16; it++) {
        int idx = it * 256 + tid;                 // 0..4095
        int row = idx >> 6, col = idx & 63;
        int kk  = (row & 31) * 2;
        float s  = gg[col] * rsqrtf(vv[col] + EPSV);
        float w0 = w[col * wstride + wcol0 + kk]     * s;
        float w1 = w[col * wstride + wcol0 + kk + 1] * s;
        uint32_t hiw, low;
        split2(w0, w1, hiw, low);
        packB[row * 64 + (col ^ ((row & 3) << 3))] = (row < 32) ? hiw : low;
    }

    // ---- A fragments from global: lane-exact m16n8k16 layout ----
    const int m0 = blockIdx.x * 128 + wid * 16;
    const float* r0 = x + (size_t)(m0 + gq) * 64;
    const float* r1 = x + (size_t)(m0 + gq + 8) * 64;
    uint32_t Ah[4][4], Al[4][4];
    #pragma unroll
    for (int ks = 0; ks < 4; ks++) {
        float2 v0 = *(const float2*)(r0 + 16 * ks + 2 * tq);
        float2 v1 = *(const float2*)(r1 + 16 * ks + 2 * tq);
        float2 v2 = *(const float2*)(r0 + 16 * ks + 2 * tq + 8);
        float2 v3 = *(const float2*)(r1 + 16 * ks + 2 * tq + 8);
        split2(v0.x, v0.y, Ah[ks][0], Al[ks][0]);
        split2(v1.x, v1.y, Ah[ks][1], Al[ks][1]);
        split2(v2.x, v2.y, Ah[ks][2], Al[ks][2]);
        split2(v3.x, v3.y, Ah[ks][3], Al[ks][3]);
    }

    float acc[8][4];
    #pragma unroll
    for (int nt = 0; nt < 8; nt++)
        #pragma unroll
        for (int r = 0; r < 4; r++) acc[nt][r] = 0.0f;

    __syncthreads();

    // ---- 3 chains x 4 k-steps x 8 n-tiles ----
    #pragma unroll
    for (int c = 0; c < 3; c++) {
        const uint32_t (*Af)[4] = (c == 2) ? Al : Ah;
        const int rb = (c == 1) ? 32 : 0;
        #pragma unroll
        for (int ks = 0; ks < 4; ks++) {
            const int r0i = (rb + 8 * ks + tq) * 64;
            const int r1i = (rb + 8 * ks + tq + 4) * 64;
            const int csw = tq << 3;
            #pragma unroll
            for (int nt = 0; nt < 8; nt++) {
                int coff = (8 * nt + gq) ^ csw;
                uint32_t b0 = packB[r0i + coff];
                uint32_t b1 = packB[r1i + coff];
                mma16816(acc[nt], Af[ks], b0, b1);
            }
        }
    }

    // ---- epilogue: +bias, relu, float2 stores ----
    float* o = (DST == 0) ? outp : ((DST == 1) ? g_upfeat : g_pre);
    float* o0 = o + (size_t)(m0 + gq) * 64;
    float* o1 = o + (size_t)(m0 + gq + 8) * 64;
    #pragma unroll
    for (int nt = 0; nt < 8; nt++) {
        int col = 8 * nt + 2 * tq;
        float2 fbp = *(float2*)&fb[col];
        float2 u, v;
        u.x = acc[nt][0] + fbp.x; u.y = acc[nt][1] + fbp.y;
        v.x = acc[nt][2] + fbp.x; v.y = acc[nt][3] + fbp.y;
        if (RELU) {
            u.x = fmaxf(u.x, 0.f); u.y = fmaxf(u.y, 0.f);
            v.x = fmaxf(v.x, 0.f); v.y = fmaxf(v.y, 0.f);
        }
        *(float2*)(o0 + col) = u;
        *(float2*)(o1 + col) = v;
    }
}

// ===================== logit + exp + denom (one MPAIR pass) =====================
__global__ void logit_kernel(const float* __restrict__ p1,
                             const float* __restrict__ p2,
                             const int*   __restrict__ knn,
                             const float* __restrict__ ws1,
                             const float* __restrict__ gsv,
                             const float* __restrict__ vsv,
                             const float* __restrict__ ws2,
                             const float* __restrict__ bs2)
{
    __shared__ float sw3[64][3];
    __shared__ float sw2[64];
    int tid = threadIdx.x;
    if (tid < 64) {
        float s = gsv[tid] * rsqrtf(vsv[tid] + EPSV);
        sw3[tid][0] = ws1[tid * 67 + 0] * s;
        sw3[tid][1] = ws1[tid * 67 + 1] * s;
        sw3[tid][2] = ws1[tid * 67 + 2] * s;
        sw2[tid]    = ws2[tid];
    }
    __syncthreads();

    int mi = blockIdx.x * blockDim.x + tid;
    int j  = mi >> 4;
    int i  = knn[mi];
    float prx = p1[i*3+0] - p2[j*3+0];
    float pry = p1[i*3+1] - p2[j*3+1];
    float prz = p1[i*3+2] - p2[j*3+2];

    float acc = 0.0f;
    const float4* pre4 = (const float4*)(g_pre + (size_t)j * 64);
    #pragma unroll
    for (int c4 = 0; c4 < 16; c4++) {
        float4 pv = pre4[c4];
        int c = c4 * 4;
        float h;
        h = fmaf(prx, sw3[c+0][0], fmaf(pry, sw3[c+0][1], fmaf(prz, sw3[c+0][2], pv.x)));
        h = fmaxf(h, 0.0f); acc = fmaf(h, sw2[c+0], acc);
        h = fmaf(prx, sw3[c+1][0], fmaf(pry, sw3[c+1][1], fmaf(prz, sw3[c+1][2], pv.y)));
        h = fmaxf(h, 0.0f); acc = fmaf(h, sw2[c+1], acc);
        h = fmaf(prx, sw3[c+2][0], fmaf(pry, sw3[c+2][1], fmaf(prz, sw3[c+2][2], pv.z)));
        h = fmaxf(h, 0.0f); acc = fmaf(h, sw2[c+2], acc);
        h = fmaf(prx, sw3[c+3][0], fmaf(pry, sw3[c+3][1], fmaf(prz, sw3[c+3][2], pv.w)));
        h = fmaxf(h, 0.0f); acc = fmaf(h, sw2[c+3], acc);
    }
    float ev = __expf(acc + bs2[0]);
    g_e[mi] = ev;
    atomicAdd(&g_denom[i], ev);
}

// ===================== weighted scatter =====================
__global__ void scatter_kernel(const int* __restrict__ knn, float* __restrict__ out) {
    int gw   = (blockIdx.x * blockDim.x + threadIdx.x) >> 5;
    int lane = threadIdx.x & 31;
    #pragma unroll
    for (int r = 0; r < 4; r++) {
        int mi = gw * 4 + r;
        int j  = mi >> 4;
        int i  = knn[mi];
        float prob = g_e[mi] / g_denom[i];
        float u0 = g_upfeat[(size_t)j * 64 + lane];
        float u1 = g_upfeat[(size_t)j * 64 + 32 + lane];
        atomicAdd(&out[(size_t)i * 64 + lane],      u0 * prob);
        atomicAdd(&out[(size_t)i * 64 + 32 + lane], u1 * prob);
    }
}

extern "C" void kernel_launch(void* const* d_in, const int* in_sizes, int n_in,
                              void* d_out, int out_size)
{
    const float* p1  = (const float*)d_in[0];
    const float* p2  = (const float*)d_in[1];
    const float* x1  = (const float*)d_in[2];
    const float* x2  = (const float*)d_in[3];
    const int*   knn = (const int*)  d_in[4];
    const float* w1  = (const float*)d_in[5];
    const float* b1  = (const float*)d_in[6];
    const float* g1  = (const float*)d_in[7];
    const float* be1 = (const float*)d_in[8];
    const float* m1  = (const float*)d_in[9];
    const float* v1  = (const float*)d_in[10];
    const float* w2  = (const float*)d_in[11];
    const float* b2  = (const float*)d_in[12];
    const float* g2  = (const float*)d_in[13];
    const float* be2 = (const float*)d_in[14];
    const float* m2  = (const float*)d_in[15];
    const float* v2  = (const float*)d_in[16];
    const float* ws1 = (const float*)d_in[17];
    const float* bs1 = (const float*)d_in[18];
    const float* gs  = (const float*)d_in[19];
    const float* bes = (const float*)d_in[20];
    const float* ms  = (const float*)d_in[21];
    const float* vs  = (const float*)d_in[22];
    const float* ws2 = (const float*)d_in[23];
    const float* bs2 = (const float*)d_in[24];
    float* out = (float*)d_out;

    init_kernel<<<N1/256, 256>>>();

    // skip branch: y1 -> d_out (initializes every output element)
    gemm_mma_kernel<true, 0><<<N1/128, 256>>>(x1, w1, 64, 0, b1, g1, be1, m1, v1, out);
    // up_feat = relu(bn(x2 @ w2^T))
    gemm_mma_kernel<true, 1><<<N2/128, 256>>>(x2, w2, 64, 0, b2, g2, be2, m2, v2, nullptr);
    // pre = x2-part of channel_shrinker first linear (BN folded, no relu)
    gemm_mma_kernel<false, 2><<<N2/128, 256>>>(x2, ws1, 67, 3, bs1, gs, bes, ms, vs, nullptr);

    // logit + exp + denom in one MPAIR pass
    logit_kernel<<<MPAIR/256, 256>>>(p1, p2, knn, ws1, gs, vs, ws2, bs2);
    // weighted scatter on top of y1
    scatter_kernel<<<MPAIR/4/8, 256>>>(knn, out);
}

// round 5
// speedup vs baseline: 1.4620x; 1.4620x over previous
#include <cuda_runtime.h>
#include <cuda_bf16.h>
#include <cstdint>

#define N1 262144
#define N2 65536
#define KNN 16
#define MPAIR (N2*KNN)
#define EPSV 1e-5f

// ---- static scratch (no runtime allocation allowed) ----
__device__ float g_upfeat[N2*64];   // relu(bn(x2@w2^T))
__device__ float g_pre[N2*64];      // x2-part of shrinker linear
__device__ float g_e[MPAIR];        // exp(logit)
__device__ float g_denom[N1];       // softmax denominator

__global__ void init_kernel() {
    int i = blockIdx.x * blockDim.x + threadIdx.x;
    if (i < N1) g_denom[i] = 0.0f;
}

// bf16 mma (baseline ISA, sm_80+; lowers to HMMA on sm_103 tensor pipe)
__device__ __forceinline__ void mma16816(float* d, const uint32_t* a, uint32_t b0, uint32_t b1) {
    asm volatile(
        "mma.sync.aligned.m16n8k16.row.col.f32.bf16.bf16.f32 "
        "{%0,%1,%2,%3}, {%4,%5,%6,%7}, {%8,%9}, {%0,%1,%2,%3};"
        : "+f"(d[0]), "+f"(d[1]), "+f"(d[2]), "+f"(d[3])
        : "r"(a[0]), "r"(a[1]), "r"(a[2]), "r"(a[3]), "r"(b0), "r"(b1));
}

// split (f0,f1) into packed bf16 hi-pair and lo-pair (residual)
__device__ __forceinline__ void split2(float f0, float f1, uint32_t& hi, uint32_t& lo) {
    __nv_bfloat16 h0 = __float2bfloat16_rn(f0);
    __nv_bfloat16 h1 = __float2bfloat16_rn(f1);
    __nv_bfloat162 hp; hp.x = h0; hp.y = h1;
    __nv_bfloat162 lp = __floats2bfloat162_rn(f0 - __bfloat162float(h0),
                                              f1 - __bfloat162float(h1));
    hi = *(uint32_t*)&hp;
    lo = *(uint32_t*)&lp;
}

// Pack BN-folded W into smem as bf16 hi/lo k-pairs in the k-PERMUTED layout.
// Logical k within step ks: thread tq's b0 pair -> phys cols 16ks+4tq..+1,
// b1 pair -> phys cols 16ks+4tq+2..+3. Row r in [0,32): hi, [32,64): lo.
// Row rb+8ks+q (q<4 -> b0 pair for tq=q; q>=4 -> b1 pair for tq=q-4).
__device__ __forceinline__ void fill_packB(uint32_t* packB, float* fb,
                                           const float* __restrict__ w, int wstride, int wcol0,
                                           const float* __restrict__ bb,
                                           const float* __restrict__ gg,
                                           const float* __restrict__ be,
                                           const float* __restrict__ mm,
                                           const float* __restrict__ vv,
                                           int tid)
{
    if (tid < 64) {
        float s = gg[tid] * rsqrtf(vv[tid] + EPSV);
        fb[tid] = (bb[tid] - mm[tid]) * s + be[tid];
    }
    #pragma unroll
    for (int it = 0; it < 16; it++) {
        int idx = it * 256 + tid;                 // 0..4095
        int row = idx >> 6, col = idx & 63;
        int r31 = row & 31;
        int ks = r31 >> 3, q = r31 & 7;
        int kk = 16 * ks + ((q < 4) ? 4 * q : 4 * (q - 4) + 2);
        float s  = gg[col] * rsqrtf(vv[col] + EPSV);
        float w0 = w[col * wstride + wcol0 + kk]     * s;
        float w1 = w[col * wstride + wcol0 + kk + 1] * s;
        uint32_t hiw, low;
        split2(w0, w1, hiw, low);
        packB[row * 64 + (col ^ ((row & 3) << 3))] = (row < 32) ? hiw : low;
    }
}

// Load A fragments for a 16-row tile: one float4 per row per k-step (k-permuted).
__device__ __forceinline__ void load_A(const float* __restrict__ x, int m0, int gq, int tq,
                                       uint32_t Ah[4][4], uint32_t Al[4][4])
{
    const float4* r0 = (const float4*)(x + (size_t)(m0 + gq) * 64);
    const float4* r1 = (const float4*)(x + (size_t)(m0 + gq + 8) * 64);
    #pragma unroll
    for (int ks = 0; ks < 4; ks++) {
        float4 v0 = r0[4 * ks + tq];
        float4 v1 = r1[4 * ks + tq];
        split2(v0.x, v0.y, Ah[ks][0], Al[ks][0]);
        split2(v1.x, v1.y, Ah[ks][1], Al[ks][1]);
        split2(v0.z, v0.w, Ah[ks][2], Al[ks][2]);
        split2(v1.z, v1.w, Ah[ks][3], Al[ks][3]);
    }
}

// 3 accumulating chains (Ah*Bh + Ah*Bl + Al*Bh) over one packB.
__device__ __forceinline__ void run_chains(float acc[8][4], const uint32_t* packB,
                                           const uint32_t Ah[4][4], const uint32_t Al[4][4],
                                           int gq, int tq)
{
    const int csw = tq << 3;
    #pragma unroll
    for (int c = 0; c < 3; c++) {
        const uint32_t (*Af)[4] = (c == 2) ? Al : Ah;
        const int rb = (c == 1) ? 32 : 0;
        #pragma unroll
        for (int ks = 0; ks < 4; ks++) {
            const int r0i = (rb + 8 * ks + tq) * 64;
            const int r1i = (rb + 8 * ks + tq + 4) * 64;
            #pragma unroll
            for (int nt = 0; nt < 8; nt++) {
                int coff = (8 * nt + gq) ^ csw;
                mma16816(acc[nt], Af[ks], packB[r0i + coff], packB[r1i + coff]);
            }
        }
    }
}

__device__ __forceinline__ void epilogue(float acc[8][4], const float* fb,
                                         float* __restrict__ o, int m0, int gq, int tq, bool relu)
{
    float* o0 = o + (size_t)(m0 + gq) * 64;
    float* o1 = o + (size_t)(m0 + gq + 8) * 64;
    #pragma unroll
    for (int nt = 0; nt < 8; nt++) {
        int col = 8 * nt + 2 * tq;
        float2 fbp = *(float2*)&fb[col];
        float2 u, v;
        u.x = acc[nt][0] + fbp.x; u.y = acc[nt][1] + fbp.y;
        v.x = acc[nt][2] + fbp.x; v.y = acc[nt][3] + fbp.y;
        if (relu) {
            u.x = fmaxf(u.x, 0.f); u.y = fmaxf(u.y, 0.f);
            v.x = fmaxf(v.x, 0.f); v.y = fmaxf(v.y, 0.f);
        }
        *(float2*)(o0 + col) = u;
        *(float2*)(o1 + col) = v;
    }
}

// ============ N1 GEMM: y1 = relu(bn(x1@w1^T)) -> d_out, persistent blocks ============
__global__ void __launch_bounds__(256)
gemm_n1_kernel(const float* __restrict__ x,
               const float* __restrict__ w,
               const float* __restrict__ bb, const float* __restrict__ gg,
               const float* __restrict__ be, const float* __restrict__ mm,
               const float* __restrict__ vv,
               float* __restrict__ outp)
{
    __shared__ uint32_t packB[64 * 64];
    __shared__ float fb[64];
    const int tid = threadIdx.x, wid = tid >> 5, lane = tid & 31;
    const int gq = lane >> 2, tq = lane & 3;

    fill_packB(packB, fb, w, 64, 0, bb, gg, be, mm, vv, tid);
    __syncthreads();

    for (int t = blockIdx.x; t < N1 / 128; t += gridDim.x) {
        const int m0 = t * 128 + wid * 16;
        uint32_t Ah[4][4], Al[4][4];
        load_A(x, m0, gq, tq, Ah, Al);
        float acc[8][4];
        #pragma unroll
        for (int nt = 0; nt < 8; nt++)
            #pragma unroll
            for (int r = 0; r < 4; r++) acc[nt][r] = 0.0f;
        run_chains(acc, packB, Ah, Al, gq, tq);
        epilogue(acc, fb, outp, m0, gq, tq, true);
    }
}

// ============ N2 fused GEMM: upfeat (w2, relu) + pre (ws1[:,3:], no relu) ============
__global__ void __launch_bounds__(256)
gemm_n2_kernel(const float* __restrict__ x,
               const float* __restrict__ w2,
               const float* __restrict__ b2, const float* __restrict__ g2,
               const float* __restrict__ be2, const float* __restrict__ m2,
               const float* __restrict__ v2,
               const float* __restrict__ ws1,
               const float* __restrict__ bs1, const float* __restrict__ gs,
               const float* __restrict__ bes, const float* __restrict__ ms,
               const float* __restrict__ vs)
{
    __shared__ uint32_t packB2[64 * 64];
    __shared__ uint32_t packBs[64 * 64];
    __shared__ float fb2[64], fbs[64];
    const int tid = threadIdx.x, wid = tid >> 5, lane = tid & 31;
    const int gq = lane >> 2, tq = lane & 3;

    fill_packB(packB2, fb2, w2, 64, 0, b2, g2, be2, m2, v2, tid);
    fill_packB(packBs, fbs, ws1, 67, 3, bs1, gs, bes, ms, vs, tid);
    __syncthreads();

    for (int t = blockIdx.x; t < N2 / 128; t += gridDim.x) {
        const int m0 = t * 128 + wid * 16;
        uint32_t Ah[4][4], Al[4][4];
        load_A(x, m0, gq, tq, Ah, Al);

        float acc[8][4];
        #pragma unroll
        for (int nt = 0; nt < 8; nt++)
            #pragma unroll
            for (int r = 0; r < 4; r++) acc[nt][r] = 0.0f;
        run_chains(acc, packB2, Ah, Al, gq, tq);
        epilogue(acc, fb2, g_upfeat, m0, gq, tq, true);

        #pragma unroll
        for (int nt = 0; nt < 8; nt++)
            #pragma unroll
            for (int r = 0; r < 4; r++) acc[nt][r] = 0.0f;
        run_chains(acc, packBs, Ah, Al, gq, tq);
        epilogue(acc, fbs, g_pre, m0, gq, tq, false);
    }
}

// ===================== logit + exp + denom (one MPAIR pass) =====================
__global__ void logit_kernel(const float* __restrict__ p1,
                             const float* __restrict__ p2,
                             const int*   __restrict__ knn,
                             const float* __restrict__ ws1,
                             const float* __restrict__ gsv,
                             const float* __restrict__ vsv,
                             const float* __restrict__ ws2,
                             const float* __restrict__ bs2)
{
    __shared__ float sw3[64][3];
    __shared__ float sw2[64];
    int tid = threadIdx.x;
    if (tid < 64) {
        float s = gsv[tid] * rsqrtf(vsv[tid] + EPSV);
        sw3[tid][0] = ws1[tid * 67 + 0] * s;
        sw3[tid][1] = ws1[tid * 67 + 1] * s;
        sw3[tid][2] = ws1[tid * 67 + 2] * s;
        sw2[tid]    = ws2[tid];
    }
    __syncthreads();

    int mi = blockIdx.x * blockDim.x + tid;
    int j  = mi >> 4;
    int i  = knn[mi];
    float prx = p1[i*3+0] - p2[j*3+0];
    float pry = p1[i*3+1] - p2[j*3+1];
    float prz = p1[i*3+2] - p2[j*3+2];

    float acc = 0.0f;
    const float4* pre4 = (const float4*)(g_pre + (size_t)j * 64);
    #pragma unroll
    for (int c4 = 0; c4 < 16; c4++) {
        float4 pv = pre4[c4];
        int c = c4 * 4;
        float h;
        h = fmaf(prx, sw3[c+0][0], fmaf(pry, sw3[c+0][1], fmaf(prz, sw3[c+0][2], pv.x)));
        h = fmaxf(h, 0.0f); acc = fmaf(h, sw2[c+0], acc);
        h = fmaf(prx, sw3[c+1][0], fmaf(pry, sw3[c+1][1], fmaf(prz, sw3[c+1][2], pv.y)));
        h = fmaxf(h, 0.0f); acc = fmaf(h, sw2[c+1], acc);
        h = fmaf(prx, sw3[c+2][0], fmaf(pry, sw3[c+2][1], fmaf(prz, sw3[c+2][2], pv.z)));
        h = fmaxf(h, 0.0f); acc = fmaf(h, sw2[c+2], acc);
        h = fmaf(prx, sw3[c+3][0], fmaf(pry, sw3[c+3][1], fmaf(prz, sw3[c+3][2], pv.w)));
        h = fmaxf(h, 0.0f); acc = fmaf(h, sw2[c+3], acc);
    }
    float ev = __expf(acc + bs2[0]);
    g_e[mi] = ev;
    atomicAdd(&g_denom[i], ev);
}

// ===================== weighted scatter =====================
__global__ void scatter_kernel(const int* __restrict__ knn, float* __restrict__ out) {
    int gw   = (blockIdx.x * blockDim.x + threadIdx.x) >> 5;
    int lane = threadIdx.x & 31;
    #pragma unroll
    for (int r = 0; r < 4; r++) {
        int mi = gw * 4 + r;
        int j  = mi >> 4;
        int i  = knn[mi];
        float prob = g_e[mi] / g_denom[i];
        float u0 = g_upfeat[(size_t)j * 64 + lane];
        float u1 = g_upfeat[(size_t)j * 64 + 32 + lane];
        atomicAdd(&out[(size_t)i * 64 + lane],      u0 * prob);
        atomicAdd(&out[(size_t)i * 64 + 32 + lane], u1 * prob);
    }
}

extern "C" void kernel_launch(void* const* d_in, const int* in_sizes, int n_in,
                              void* d_out, int out_size)
{
    const float* p1  = (const float*)d_in[0];
    const float* p2  = (const float*)d_in[1];
    const float* x1  = (const float*)d_in[2];
    const float* x2  = (const float*)d_in[3];
    const int*   knn = (const int*)  d_in[4];
    const float* w1  = (const float*)d_in[5];
    const float* b1  = (const float*)d_in[6];
    const float* g1  = (const float*)d_in[7];
    const float* be1 = (const float*)d_in[8];
    const float* m1  = (const float*)d_in[9];
    const float* v1  = (const float*)d_in[10];
    const float* w2  = (const float*)d_in[11];
    const float* b2  = (const float*)d_in[12];
    const float* g2  = (const float*)d_in[13];
    const float* be2 = (const float*)d_in[14];
    const float* m2  = (const float*)d_in[15];
    const float* v2  = (const float*)d_in[16];
    const float* ws1 = (const float*)d_in[17];
    const float* bs1 = (const float*)d_in[18];
    const float* gs  = (const float*)d_in[19];
    const float* bes = (const float*)d_in[20];
    const float* ms  = (const float*)d_in[21];
    const float* vs  = (const float*)d_in[22];
    const float* ws2 = (const float*)d_in[23];
    const float* bs2 = (const float*)d_in[24];
    float* out = (float*)d_out;

    init_kernel<<<N1/256, 256>>>();

    // skip branch: y1 -> d_out (persistent, initializes every output element)
    gemm_n1_kernel<<<296, 256>>>(x1, w1, b1, g1, be1, m1, v1, out);
    // fused: up_feat + pre (share x2 reads and A conversion)
    gemm_n2_kernel<<<296, 256>>>(x2, w2, b2, g2, be2, m2, v2,
                                 ws1, bs1, gs, bes, ms, vs);

    // logit + exp + denom in one MPAIR pass
    logit_kernel<<<MPAIR/256, 256>>>(p1, p2, knn, ws1, gs, vs, ws2, bs2);
    // weighted scatter on top of y1
    scatter_kernel<<<MPAIR/4/8, 256>>>(knn, out);
}